// round 3
// baseline (speedup 1.0000x reference)
#include <cuda_runtime.h>

typedef unsigned long long ull;

#define NTHREADS 256
#define GROUP 16
#define GPART 32
#define PTS_PER_BLOCK 32   // (256/16) groups * 2 points packed per lane

// ---------------- packed f32x2 helpers (sm_103a) ----------------
__device__ __forceinline__ ull fma2(ull a, ull b, ull c) {
    ull d; asm("fma.rn.f32x2 %0,%1,%2,%3;" : "=l"(d) : "l"(a), "l"(b), "l"(c)); return d;
}
__device__ __forceinline__ ull mul2(ull a, ull b) {
    ull d; asm("mul.rn.f32x2 %0,%1,%2;" : "=l"(d) : "l"(a), "l"(b)); return d;
}
__device__ __forceinline__ ull pack2(float lo, float hi) {
    ull d; asm("mov.b64 %0,{%1,%2};" : "=l"(d) : "f"(lo), "f"(hi)); return d;
}
__device__ __forceinline__ void unpack2(ull v, float& lo, float& hi) {
    asm("mov.b64 {%0,%1},%2;" : "=f"(lo), "=f"(hi) : "l"(v));
}

#define ONE2    0x3F8000003F800000ull
#define NEGONE2 0xBF800000BF800000ull
#define NEGTWO2 0xC0000000C0000000ull
#define SIX2    0x40C0000040C00000ull

// ---------------- lb/ub reduction ----------------
__device__ unsigned g_pmin[GPART];
__device__ unsigned g_pmax[GPART];

__device__ __forceinline__ unsigned enc_f(float f) {
    unsigned u = __float_as_uint(f);
    return (u & 0x80000000u) ? ~u : (u | 0x80000000u);
}
__device__ __forceinline__ float dec_f(unsigned e) {
    unsigned u = (e & 0x80000000u) ? (e ^ 0x80000000u) : ~e;
    return __uint_as_float(u);
}

__global__ void k_partial_minmax(const float* __restrict__ X, int n) {
    __shared__ unsigned smn[8], smx[8];
    unsigned mn = 0xFFFFFFFFu, mx = 0u;
    for (int i = blockIdx.x * blockDim.x + threadIdx.x; i < n;
         i += gridDim.x * blockDim.x) {
        unsigned e = enc_f(X[3 * i]);
        mn = min(mn, e); mx = max(mx, e);
    }
    #pragma unroll
    for (int o = 16; o; o >>= 1) {
        mn = min(mn, __shfl_xor_sync(0xffffffffu, mn, o));
        mx = max(mx, __shfl_xor_sync(0xffffffffu, mx, o));
    }
    int w = threadIdx.x >> 5;
    if ((threadIdx.x & 31) == 0) { smn[w] = mn; smx[w] = mx; }
    __syncthreads();
    if (threadIdx.x == 0) {
        #pragma unroll
        for (int i = 1; i < 8; i++) { mn = min(mn, smn[i]); mx = max(mx, smx[i]); }
        g_pmin[blockIdx.x] = mn;
        g_pmax[blockIdx.x] = mx;
    }
}

// Jet order: 0:val 1:x 2:y 3:t 4:xx 5:xy 6:yy 7:xt 8:yt 9:xxx 10:xxy 11:xyy 12:yyy
// smem rows: 0 = tanh(z0), 1..6 = z of jets 1..6, 7 = zeros, 8 = z0 (staging for tanh)
// combine: h = s*( z - 2h0(zf*zde + ze*zdf + zd*zef) + (6h0^2-2) zd*ze*zf ), s=1-h0^2
// operand rows per jet-lane (row 7 = zero masks unused terms; lanes 13-15 dummy):
__constant__ int c_rd[16]  = {7,7,7,7, 1,1,2,1,2, 1,1,1,2, 7,7,7};
__constant__ int c_re[16]  = {7,7,7,7, 1,2,2,3,3, 1,1,2,2, 7,7,7};
__constant__ int c_rf[16]  = {7,7,7,7, 7,7,7,7,7, 1,2,2,2, 7,7,7};
__constant__ int c_rde[16] = {7,7,7,7, 7,7,7,7,7, 4,4,5,6, 7,7,7};
__constant__ int c_rdf[16] = {7,7,7,7, 7,7,7,7,7, 4,5,5,6, 7,7,7};
__constant__ int c_ref[16] = {7,7,7,7, 1,2,2,3,3, 4,5,6,6, 7,7,7};

#define ROWS11 11   // row stride in ulonglong2 units (odd mod 8 -> spread quads)

__device__ __forceinline__ ull combine1(ull zown, ull h0, ull zd, ull ze, ull zf,
                                        ull zde, ull zdf, ull zef) {
    ull hq  = mul2(h0, h0);
    ull s   = fma2(hq, NEGONE2, ONE2);     // 1 - h0^2
    ull C   = fma2(hq, SIX2, NEGTWO2);     // 6h0^2 - 2
    ull T   = mul2(zf, zde);
    T       = fma2(ze, zdf, T);
    T       = fma2(zd, zef, T);
    ull cub = mul2(mul2(zd, ze), zf);
    ull n2h = mul2(h0, NEGTWO2);
    ull r   = fma2(n2h, T, zown);
    r       = fma2(C, cub, r);
    return mul2(s, r);
}

template <int DIN, int DOUT>
__device__ __forceinline__ void layer_step(
    ull (&h)[20],
    const ull* __restrict__ Wl,   // [DIN][DOUT] pre-splatted (w,w)
    const ull* __restrict__ bl,   // [DOUT] pre-splatted
    ulonglong2* grp, int lane, bool isjet0,
    int od, int oe, int of, int ode, int odf, int oef)
{
    constexpr int NC = DOUT / 2;   // ulonglong2 chunks (2 units each)
    ull z[DOUT];

    const ulonglong2* Bv = reinterpret_cast<const ulonglong2*>(bl);
    #pragma unroll
    for (int c = 0; c < NC; c++) {
        ulonglong2 b = Bv[c];
        z[2 * c]     = isjet0 ? b.x : 0ull;
        z[2 * c + 1] = isjet0 ? b.y : 0ull;
    }

    const ulonglong2* Wv = reinterpret_cast<const ulonglong2*>(Wl);
    #pragma unroll
    for (int i = 0; i < DIN; i++) {
        ull hh = h[i];
        #pragma unroll
        for (int c = 0; c < NC; c++) {
            ulonglong2 w = Wv[i * NC + c];
            z[2 * c]     = fma2(hh, w.x, z[2 * c]);
            z[2 * c + 1] = fma2(hh, w.y, z[2 * c + 1]);
        }
    }

    __syncwarp();   // previous combine reads complete before overwriting rows
    if (lane <= 6) {
        int row = isjet0 ? 8 : lane;
        ulonglong2* dst = grp + row * ROWS11;
        #pragma unroll
        for (int c = 0; c < NC; c++) dst[c] = make_ulonglong2(z[2 * c], z[2 * c + 1]);
    }
    __syncwarp();   // z rows + z0 staged

    if (lane < NC) {   // distributed tanh of z0 -> row 0
        ulonglong2 v = grp[8 * ROWS11 + lane];
        float a, b, cc, d;
        unpack2(v.x, a, b); unpack2(v.y, cc, d);
        v.x = pack2(tanhf(a), tanhf(b));
        v.y = pack2(tanhf(cc), tanhf(d));
        grp[lane] = v;
    }
    __syncwarp();   // h0 row visible

    #pragma unroll
    for (int c = 0; c < NC; c++) {
        ulonglong2 h0v = grp[c];
        ulonglong2 zdv = grp[od  + c];
        ulonglong2 zev = grp[oe  + c];
        ulonglong2 zfv = grp[of  + c];
        ulonglong2 dev = grp[ode + c];
        ulonglong2 dfv = grp[odf + c];
        ulonglong2 efv = grp[oef + c];
        ull h0a = combine1(z[2 * c],     h0v.x, zdv.x, zev.x, zfv.x, dev.x, dfv.x, efv.x);
        ull h0b = combine1(z[2 * c + 1], h0v.y, zdv.y, zev.y, zfv.y, dev.y, dfv.y, efv.y);
        h[2 * c]     = isjet0 ? h0v.x : h0a;
        h[2 * c + 1] = isjet0 ? h0v.y : h0b;
    }
}

__device__ __forceinline__ void emit_point(float* __restrict__ out, int n, int g,
                                           const float* psi, const float* pp,
                                           float l1, float l2) {
    if (g >= n) return;
    float u    =  psi[2];
    float v    = -psi[1];
    float pv   =  pp[0];
    float p_x  =  pp[1];
    float p_y  =  pp[2];
    float u_t  =  psi[8];
    float u_x  =  psi[5];
    float u_y  =  psi[6];
    float v_t  = -psi[7];
    float v_x  = -psi[4];
    float v_y  = -psi[5];
    float u_xx =  psi[10];
    float u_yy =  psi[12];
    float v_xx = -psi[9];
    float v_yy = -psi[11];
    float f_u = u_t + l1 * (u * u_x + v * u_y) + p_x - l2 * (u_xx + u_yy);
    float f_v = v_t + l1 * (u * v_x + v * v_y) + p_y - l2 * (v_xx + v_yy);
    out[0 * n + g] = u;
    out[1 * n + g] = v;
    out[2 * n + g] = pv;
    out[3 * n + g] = f_u;
    out[4 * n + g] = f_v;
}

__global__ void __launch_bounds__(NTHREADS)
pinn_kernel(const float* __restrict__ X,
            const float* __restrict__ W1, const float* __restrict__ b1,
            const float* __restrict__ W2, const float* __restrict__ b2,
            const float* __restrict__ W3, const float* __restrict__ b3,
            const float* __restrict__ W4, const float* __restrict__ b4,
            const float* __restrict__ W5, const float* __restrict__ b5,
            const float* __restrict__ W6, const float* __restrict__ b6,
            const float* __restrict__ W7, const float* __restrict__ b7,
            const float* __restrict__ W8, const float* __restrict__ b8,
            const float* __restrict__ lam1p, const float* __restrict__ lam2p,
            float* __restrict__ out, int n)
{
    __shared__ ull Wsh[2152];                // pre-splatted weights (padded)
    __shared__ ull bsh[128];                 // pre-splatted biases
    __shared__ ulonglong2 zbuf[8][2][100];   // [warp][group][9 rows * 11 + pad]

    const int tid = threadIdx.x;

    const int WOFF[8] = {0, 12, 72, 472, 872, 1272, 1672, 2072};
    const int LDIN[8] = {3, 3, 20, 20, 20, 20, 20, 20};
    const int DSRC[8] = {3, 20, 20, 20, 20, 20, 20, 2};
    const int DPAD[8] = {4, 20, 20, 20, 20, 20, 20, 4};
    const int BOFF[8] = {0, 4, 24, 44, 64, 84, 104, 124};
    const float* Wg[8] = {W1, W2, W3, W4, W5, W6, W7, W8};
    const float* Bg[8] = {b1, b2, b3, b4, b5, b6, b7, b8};

    #pragma unroll
    for (int l = 0; l < 8; l++) {
        int tot = LDIN[l] * DPAD[l];
        for (int i = tid; i < tot; i += NTHREADS) {
            int r = i / DPAD[l], c = i % DPAD[l];
            float w = (c < DSRC[l]) ? Wg[l][r * DSRC[l] + c] : 0.0f;
            Wsh[WOFF[l] + i] = pack2(w, w);
        }
        for (int i = tid; i < DPAD[l]; i += NTHREADS) {
            float b = (i < DSRC[l]) ? Bg[l][i] : 0.0f;
            bsh[BOFF[l] + i] = pack2(b, b);
        }
    }
    __syncthreads();

    // fold lb/ub partials (uniform, broadcast)
    unsigned mn = 0xFFFFFFFFu, mx = 0u;
    #pragma unroll
    for (int i = 0; i < GPART; i++) {
        mn = min(mn, g_pmin[i]);
        mx = max(mx, g_pmax[i]);
    }
    const float lb = dec_f(mn);
    const float ub = dec_f(mx);
    const float sc = 2.0f / (ub - lb);

    const int warp = tid >> 5;
    const int l32  = tid & 31;
    const int grpI = l32 >> 4;
    const int lane = l32 & 15;     // = jet (13..15 dummy)
    const bool isjet0 = (lane == 0);
    ulonglong2* grp = &zbuf[warp][grpI][0];

    // zero row (row 7)
    if (lane < 10) grp[7 * ROWS11 + lane] = make_ulonglong2(0ull, 0ull);

    const int pairI = blockIdx.x * 16 + warp * 2 + grpI;
    const int pA = pairI * 2;
    const int pB = pA + 1;
    const int cA = (pA < n) ? pA : (n - 1);
    const int cB = (pB < n) ? pB : (n - 1);

    const float x0A = X[3 * cA + 0], x1A = X[3 * cA + 1], x2A = X[3 * cA + 2];
    const float x0B = X[3 * cB + 0], x1B = X[3 * cB + 1], x2B = X[3 * cB + 2];

    ull h[20];
    h[0] = 0ull; h[1] = 0ull; h[2] = 0ull;
    if (lane == 0) {
        h[0] = pack2(sc * (x0A - lb) - 1.0f, sc * (x0B - lb) - 1.0f);
        h[1] = pack2(sc * (x1A - lb) - 1.0f, sc * (x1B - lb) - 1.0f);
        h[2] = pack2(sc * (x2A - lb) - 1.0f, sc * (x2B - lb) - 1.0f);
    } else if (lane == 1) h[0] = pack2(sc, sc);
    else if (lane == 2)   h[1] = pack2(sc, sc);
    else if (lane == 3)   h[2] = pack2(sc, sc);

    const int od  = c_rd[lane]  * ROWS11;
    const int oe  = c_re[lane]  * ROWS11;
    const int of  = c_rf[lane]  * ROWS11;
    const int ode = c_rde[lane] * ROWS11;
    const int odf = c_rdf[lane] * ROWS11;
    const int oef = c_ref[lane] * ROWS11;

    layer_step<3, 4>  (h, Wsh + WOFF[0], bsh + BOFF[0], grp, lane, isjet0, od, oe, of, ode, odf, oef);
    layer_step<3, 20> (h, Wsh + WOFF[1], bsh + BOFF[1], grp, lane, isjet0, od, oe, of, ode, odf, oef);
    #pragma unroll 1
    for (int l = 0; l < 5; l++) {
        layer_step<20, 20>(h, Wsh + 72 + 400 * l, bsh + 24 + 20 * l, grp, lane, isjet0,
                           od, oe, of, ode, odf, oef);
    }
    layer_step<20, 4> (h, Wsh + WOFF[7], bsh + BOFF[7], grp, lane, isjet0, od, oe, of, ode, odf, oef);

    // epilogue: stage (psi, p) pairs of all 13 jets, lane 0 finishes both points
    __syncwarp();
    if (lane < 13) grp[lane] = make_ulonglong2(h[0], h[1]);
    __syncwarp();

    if (lane == 0) {
        float psiA[13], psiB[13], ppA[3], ppB[3];
        #pragma unroll
        for (int j = 0; j < 13; j++) {
            ulonglong2 v = grp[j];
            float a, b; unpack2(v.x, a, b);
            psiA[j] = a; psiB[j] = b;
            if (j < 3) { float c, d; unpack2(v.y, c, d); ppA[j] = c; ppB[j] = d; }
        }
        float l1 = lam1p[0];
        float l2 = lam2p[0];
        emit_point(out, n, pA, psiA, ppA, l1, l2);
        emit_point(out, n, pB, psiB, ppB, l1, l2);
    }
}

extern "C" void kernel_launch(void* const* d_in, const int* in_sizes, int n_in,
                              void* d_out, int out_size) {
    const float* X    = (const float*)d_in[0];
    const float* W1   = (const float*)d_in[1];
    const float* b1   = (const float*)d_in[2];
    const float* W2   = (const float*)d_in[3];
    const float* b2   = (const float*)d_in[4];
    const float* W3   = (const float*)d_in[5];
    const float* b3   = (const float*)d_in[6];
    const float* W4   = (const float*)d_in[7];
    const float* b4   = (const float*)d_in[8];
    const float* W5   = (const float*)d_in[9];
    const float* b5   = (const float*)d_in[10];
    const float* W6   = (const float*)d_in[11];
    const float* b6   = (const float*)d_in[12];
    const float* W7   = (const float*)d_in[13];
    const float* b7   = (const float*)d_in[14];
    const float* W8   = (const float*)d_in[15];
    const float* b8   = (const float*)d_in[16];
    const float* lam1 = (const float*)d_in[17];
    const float* lam2 = (const float*)d_in[18];
    float* out = (float*)d_out;

    int n = in_sizes[0] / 3;

    k_partial_minmax<<<GPART, 256>>>(X, n);

    int blocks = (n + PTS_PER_BLOCK - 1) / PTS_PER_BLOCK;
    pinn_kernel<<<blocks, NTHREADS>>>(X, W1, b1, W2, b2, W3, b3, W4, b4,
                                      W5, b5, W6, b6, W7, b7, W8, b8,
                                      lam1, lam2, out, n);
}

// round 5
// speedup vs baseline: 1.7246x; 1.7246x over previous
#include <cuda_runtime.h>

typedef unsigned long long ull;

#define NTHREADS 256
#define GPART 32

// ---------------- packed f32x2 helpers (sm_103a) ----------------
__device__ __forceinline__ ull fma2(ull a, ull b, ull c) {
    ull d; asm("fma.rn.f32x2 %0,%1,%2,%3;" : "=l"(d) : "l"(a), "l"(b), "l"(c)); return d;
}
__device__ __forceinline__ ull mul2(ull a, ull b) {
    ull d; asm("mul.rn.f32x2 %0,%1,%2;" : "=l"(d) : "l"(a), "l"(b)); return d;
}
__device__ __forceinline__ ull pack2(float lo, float hi) {
    ull d; asm("mov.b64 %0,{%1,%2};" : "=l"(d) : "f"(lo), "f"(hi)); return d;
}
__device__ __forceinline__ void unpack2(ull v, float& lo, float& hi) {
    asm("mov.b64 {%0,%1},%2;" : "=f"(lo), "=f"(hi) : "l"(v));
}

#define ONE2     0x3F8000003F800000ull
#define NEGONE2  0xBF800000BF800000ull
#define NEGTWO2  0xC0000000C0000000ull
#define SIX2     0x40C0000040C00000ull
#define NEGFOUR2 0xC0800000C0800000ull
#define NEGSIX2  0xC0C00000C0C00000ull

// ---------------- lb/ub reduction ----------------
__device__ unsigned g_pmin[GPART];
__device__ unsigned g_pmax[GPART];

__device__ __forceinline__ unsigned enc_f(float f) {
    unsigned u = __float_as_uint(f);
    return (u & 0x80000000u) ? ~u : (u | 0x80000000u);
}
__device__ __forceinline__ float dec_f(unsigned e) {
    unsigned u = (e & 0x80000000u) ? (e ^ 0x80000000u) : ~e;
    return __uint_as_float(u);
}

__global__ void k_partial_minmax(const float* __restrict__ X, int n) {
    __shared__ unsigned smn[8], smx[8];
    unsigned mn = 0xFFFFFFFFu, mx = 0u;
    for (int i = blockIdx.x * blockDim.x + threadIdx.x; i < n;
         i += gridDim.x * blockDim.x) {
        unsigned e = enc_f(X[3 * i]);
        mn = min(mn, e); mx = max(mx, e);
    }
    #pragma unroll
    for (int o = 16; o; o >>= 1) {
        mn = min(mn, __shfl_xor_sync(0xffffffffu, mn, o));
        mx = max(mx, __shfl_xor_sync(0xffffffffu, mx, o));
    }
    int w = threadIdx.x >> 5;
    if ((threadIdx.x & 31) == 0) { smn[w] = mn; smx[w] = mx; }
    __syncthreads();
    if (threadIdx.x == 0) {
        #pragma unroll
        for (int i = 1; i < 8; i++) { mn = min(mn, smn[i]); mx = max(mx, smx[i]); }
        g_pmin[blockIdx.x] = mn;
        g_pmax[blockIdx.x] = mx;
    }
}

// Jet order: 0:val 1:x 2:y 3:t 4:xx 5:xy 6:yy 7:xt 8:yt 9:xxx 10:xxy 11:xyy 12:yyy
// S layout per warp (ull units): [(g*2+s)*130 + jet*10 + q], q = unit-pair index.

template <int DIN, int DOUTP, int NQ, bool LAST>
__device__ __forceinline__ void layer(
    float (&ha)[20], float (&hb)[20],
    const float* __restrict__ Wl, const float* __restrict__ bl,
    ull* __restrict__ Sw, int g, int l16, bool isj0, bool jvalid,
    float* __restrict__ out, int n, int wbase, float l1, float l2)
{
    constexpr int NCU = DOUTP / 2;
    constexpr int NC2 = DOUTP / 4;
    static_assert(DOUTP % 4 == 0, "pad DOUT");

    ull za[NCU], zb[NCU];
    const ulonglong2* Bv = reinterpret_cast<const ulonglong2*>(bl);
    #pragma unroll
    for (int c = 0; c < NC2; c++) {
        ulonglong2 b = Bv[c];
        za[2 * c]     = isj0 ? b.x : 0ull;
        za[2 * c + 1] = isj0 ? b.y : 0ull;
        zb[2 * c]     = za[2 * c];
        zb[2 * c + 1] = za[2 * c + 1];
    }
    const ulonglong2* Wv = reinterpret_cast<const ulonglong2*>(Wl);
    #pragma unroll
    for (int i = 0; i < DIN; i++) {
        ull sa = pack2(ha[i], ha[i]);
        ull sb = pack2(hb[i], hb[i]);
        #pragma unroll
        for (int c = 0; c < NC2; c++) {
            ulonglong2 w = Wv[i * NC2 + c];
            za[2 * c]     = fma2(sa, w.x, za[2 * c]);
            za[2 * c + 1] = fma2(sa, w.y, za[2 * c + 1]);
            zb[2 * c]     = fma2(sb, w.x, zb[2 * c]);
            zb[2 * c + 1] = fma2(sb, w.y, zb[2 * c + 1]);
        }
    }

    __syncwarp();
    if (jvalid) {
        ulonglong2* r0 = reinterpret_cast<ulonglong2*>(Sw + ((g * 2 + 0) * 13 + l16) * 10);
        ulonglong2* r1 = reinterpret_cast<ulonglong2*>(Sw + ((g * 2 + 1) * 13 + l16) * 10);
        #pragma unroll
        for (int c = 0; c < NC2; c++) {
            r0[c] = make_ulonglong2(za[2 * c], za[2 * c + 1]);
            r1[c] = make_ulonglong2(zb[2 * c], zb[2 * c + 1]);
        }
    }
    __syncwarp();

    #pragma unroll
    for (int s = 0; s < 2; s++) {
        if (l16 < NQ) {
            const int base = (g * 2 + s) * 130 + l16;
            ull zj[13];
            #pragma unroll
            for (int jj = 0; jj < 13; jj++) zj[jj] = Sw[base + jj * 10];

            float t0, t1; unpack2(zj[0], t0, t1);
            ull t   = pack2(tanhf(t0), tanhf(t1));
            ull hq  = mul2(t, t);
            ull sv  = fma2(hq, NEGONE2, ONE2);     // s = 1 - t^2
            ull C   = fma2(hq, SIX2, NEGTWO2);     // 6t^2 - 2
            ull n2h = mul2(t, NEGTWO2);
            ull n4h = mul2(t, NEGFOUR2);
            ull n6h = mul2(t, NEGSIX2);
            ull p11 = mul2(zj[1], zj[1]);
            ull p12 = mul2(zj[1], zj[2]);
            ull p22 = mul2(zj[2], zj[2]);
            ull p13 = mul2(zj[1], zj[3]);
            ull p23 = mul2(zj[2], zj[3]);

            ull hj[13];
            hj[0] = t;
            hj[1] = mul2(sv, zj[1]);
            hj[2] = mul2(sv, zj[2]);
            hj[3] = mul2(sv, zj[3]);
            hj[4] = mul2(sv, fma2(n2h, p11, zj[4]));
            hj[5] = mul2(sv, fma2(n2h, p12, zj[5]));
            hj[6] = mul2(sv, fma2(n2h, p22, zj[6]));
            hj[7] = mul2(sv, fma2(n2h, p13, zj[7]));
            hj[8] = mul2(sv, fma2(n2h, p23, zj[8]));
            {   // xxx: z9 - 6t*z1*z4 + C*z1^3
                ull r = fma2(n6h, mul2(zj[1], zj[4]), zj[9]);
                r = fma2(C, mul2(zj[1], p11), r);
                hj[9] = mul2(sv, r);
            }
            {   // xxy: z10 - 2t*z2*z4 - 4t*z1*z5 + C*z1^2 z2
                ull r = fma2(n2h, mul2(zj[2], zj[4]), zj[10]);
                r = fma2(n4h, mul2(zj[1], zj[5]), r);
                r = fma2(C, mul2(p11, zj[2]), r);
                hj[10] = mul2(sv, r);
            }
            {   // xyy: z11 - 4t*z2*z5 - 2t*z1*z6 + C*z1 z2^2
                ull r = fma2(n4h, mul2(zj[2], zj[5]), zj[11]);
                r = fma2(n2h, mul2(zj[1], zj[6]), r);
                r = fma2(C, mul2(zj[1], p22), r);
                hj[11] = mul2(sv, r);
            }
            {   // yyy: z12 - 6t*z2*z6 + C*z2^3
                ull r = fma2(n6h, mul2(zj[2], zj[6]), zj[12]);
                r = fma2(C, mul2(zj[2], p22), r);
                hj[12] = mul2(sv, r);
            }

            if (!LAST) {
                #pragma unroll
                for (int jj = 0; jj < 13; jj++) Sw[base + jj * 10] = hj[jj];
            } else {
                // q == 0 holds units (0,1) = (psi, p) of all jets for this point
                const int pt = wbase + g * 2 + s;
                if (pt < n) {
                    float ps[13], pr0, pr1, pr2, dum;
                    #pragma unroll
                    for (int jj = 0; jj < 13; jj++) {
                        float a, b; unpack2(hj[jj], a, b);
                        ps[jj] = a;
                        if (jj == 0) pr0 = b;
                        else if (jj == 1) pr1 = b;
                        else if (jj == 2) pr2 = b;
                        else dum = b;
                    }
                    float u    =  ps[2];
                    float v    = -ps[1];
                    float p_x  =  pr1;
                    float p_y  =  pr2;
                    float u_t  =  ps[8];
                    float u_x  =  ps[5];
                    float u_y  =  ps[6];
                    float v_t  = -ps[7];
                    float v_x  = -ps[4];
                    float v_y  = -ps[5];
                    float u_xx =  ps[10];
                    float u_yy =  ps[12];
                    float v_xx = -ps[9];
                    float v_yy = -ps[11];
                    float f_u = u_t + l1 * (u * u_x + v * u_y) + p_x - l2 * (u_xx + u_yy);
                    float f_v = v_t + l1 * (u * v_x + v * v_y) + p_y - l2 * (v_xx + v_yy);
                    out[0 * n + pt] = u;
                    out[1 * n + pt] = v;
                    out[2 * n + pt] = pr0;
                    out[3 * n + pt] = f_u;
                    out[4 * n + pt] = f_v;
                }
            }
        }
    }
    __syncwarp();

    if (!LAST && jvalid) {
        const ulonglong2* r0 = reinterpret_cast<const ulonglong2*>(Sw + ((g * 2 + 0) * 13 + l16) * 10);
        const ulonglong2* r1 = reinterpret_cast<const ulonglong2*>(Sw + ((g * 2 + 1) * 13 + l16) * 10);
        #pragma unroll
        for (int c = 0; c < NC2; c++) {
            ulonglong2 v0 = r0[c];
            unpack2(v0.x, ha[4 * c],     ha[4 * c + 1]);
            unpack2(v0.y, ha[4 * c + 2], ha[4 * c + 3]);
            ulonglong2 v1 = r1[c];
            unpack2(v1.x, hb[4 * c],     hb[4 * c + 1]);
            unpack2(v1.y, hb[4 * c + 2], hb[4 * c + 3]);
        }
    }
}

__global__ void __launch_bounds__(NTHREADS, 2)
pinn_kernel(const float* __restrict__ X,
            const float* __restrict__ W1, const float* __restrict__ b1,
            const float* __restrict__ W2, const float* __restrict__ b2,
            const float* __restrict__ W3, const float* __restrict__ b3,
            const float* __restrict__ W4, const float* __restrict__ b4,
            const float* __restrict__ W5, const float* __restrict__ b5,
            const float* __restrict__ W6, const float* __restrict__ b6,
            const float* __restrict__ W7, const float* __restrict__ b7,
            const float* __restrict__ W8, const float* __restrict__ b8,
            const float* __restrict__ lam1p, const float* __restrict__ lam2p,
            float* __restrict__ out, int n)
{
    __shared__ float Wsh[2152];
    __shared__ float bsh[128];
    __shared__ __align__(16) ull Ssh[8 * 528];

    const int tid = threadIdx.x;

    const int WOFF[8] = {0, 12, 72, 472, 872, 1272, 1672, 2072};
    const int LDIN[8] = {3, 3, 20, 20, 20, 20, 20, 20};
    const int DSRC[8] = {3, 20, 20, 20, 20, 20, 20, 2};
    const int DPAD[8] = {4, 20, 20, 20, 20, 20, 20, 4};
    const int BOFF[8] = {0, 4, 24, 44, 64, 84, 104, 124};
    const float* Wg[8] = {W1, W2, W3, W4, W5, W6, W7, W8};
    const float* Bg[8] = {b1, b2, b3, b4, b5, b6, b7, b8};

    #pragma unroll
    for (int l = 0; l < 8; l++) {
        int tot = LDIN[l] * DPAD[l];
        for (int i = tid; i < tot; i += NTHREADS) {
            int r = i / DPAD[l], c = i % DPAD[l];
            Wsh[WOFF[l] + i] = (c < DSRC[l]) ? Wg[l][r * DSRC[l] + c] : 0.0f;
        }
        for (int i = tid; i < DPAD[l]; i += NTHREADS)
            bsh[BOFF[l] + i] = (i < DSRC[l]) ? Bg[l][i] : 0.0f;
    }
    __syncthreads();

    // fold lb/ub partials (uniform, broadcast)
    unsigned mn = 0xFFFFFFFFu, mx = 0u;
    #pragma unroll
    for (int i = 0; i < GPART; i++) {
        mn = min(mn, g_pmin[i]);
        mx = max(mx, g_pmax[i]);
    }
    const float lb = dec_f(mn);
    const float ub = dec_f(mx);
    const float sc = 2.0f / (ub - lb);
    const float l1 = lam1p[0];
    const float l2 = lam2p[0];

    const int warp = tid >> 5;
    const int lane = tid & 31;
    const int g    = lane >> 4;
    const int l16  = lane & 15;
    const bool jvalid = (l16 < 13);
    const bool isj0   = (l16 == 0);
    ull* Sw = Ssh + warp * 528;

    const int wbase = (blockIdx.x * 8 + warp) * 4;   // 4 points per warp
    const int ptA = min(wbase + g * 2,     n - 1);
    const int ptB = min(wbase + g * 2 + 1, n - 1);

    float ha[20], hb[20];
    #pragma unroll
    for (int k = 0; k < 20; k++) { ha[k] = 0.0f; hb[k] = 0.0f; }
    if (isj0) {
        ha[0] = sc * (X[3 * ptA + 0] - lb) - 1.0f;
        ha[1] = sc * (X[3 * ptA + 1] - lb) - 1.0f;
        ha[2] = sc * (X[3 * ptA + 2] - lb) - 1.0f;
        hb[0] = sc * (X[3 * ptB + 0] - lb) - 1.0f;
        hb[1] = sc * (X[3 * ptB + 1] - lb) - 1.0f;
        hb[2] = sc * (X[3 * ptB + 2] - lb) - 1.0f;
    } else if (l16 == 1) { ha[0] = sc; hb[0] = sc; }
    else if (l16 == 2)   { ha[1] = sc; hb[1] = sc; }
    else if (l16 == 3)   { ha[2] = sc; hb[2] = sc; }

    layer<3, 4, 2, false>(ha, hb, Wsh + 0,  bsh + 0,  Sw, g, l16, isj0, jvalid, out, n, wbase, l1, l2);
    layer<3, 20, 10, false>(ha, hb, Wsh + 12, bsh + 4,  Sw, g, l16, isj0, jvalid, out, n, wbase, l1, l2);
    #pragma unroll 1
    for (int l = 0; l < 5; l++) {
        layer<20, 20, 10, false>(ha, hb, Wsh + 72 + 400 * l, bsh + 24 + 20 * l,
                                 Sw, g, l16, isj0, jvalid, out, n, wbase, l1, l2);
    }
    layer<20, 4, 1, true>(ha, hb, Wsh + 2072, bsh + 124, Sw, g, l16, isj0, jvalid, out, n, wbase, l1, l2);
}

extern "C" void kernel_launch(void* const* d_in, const int* in_sizes, int n_in,
                              void* d_out, int out_size) {
    const float* X    = (const float*)d_in[0];
    const float* W1   = (const float*)d_in[1];
    const float* b1   = (const float*)d_in[2];
    const float* W2   = (const float*)d_in[3];
    const float* b2   = (const float*)d_in[4];
    const float* W3   = (const float*)d_in[5];
    const float* b3   = (const float*)d_in[6];
    const float* W4   = (const float*)d_in[7];
    const float* b4   = (const float*)d_in[8];
    const float* W5   = (const float*)d_in[9];
    const float* b5   = (const float*)d_in[10];
    const float* W6   = (const float*)d_in[11];
    const float* b6   = (const float*)d_in[12];
    const float* W7   = (const float*)d_in[13];
    const float* b7   = (const float*)d_in[14];
    const float* W8   = (const float*)d_in[15];
    const float* b8   = (const float*)d_in[16];
    const float* lam1 = (const float*)d_in[17];
    const float* lam2 = (const float*)d_in[18];
    float* out = (float*)d_out;

    int n = in_sizes[0] / 3;

    k_partial_minmax<<<GPART, 256>>>(X, n);

    int blocks = (n + 31) / 32;   // 32 points per block
    pinn_kernel<<<blocks, NTHREADS>>>(X, W1, b1, W2, b2, W3, b3, W4, b4,
                                      W5, b5, W6, b6, W7, b7, W8, b8,
                                      lam1, lam2, out, n);
}

// round 7
// speedup vs baseline: 2.0887x; 1.2111x over previous
#include <cuda_runtime.h>

typedef unsigned long long ull;

#define NTHREADS 256
#define GPART 32

// padded weight/bias pools
#define WTOT 2152
#define BTOT 128
__constant__ float c_W[WTOT];
__constant__ float c_b[BTOT];
__device__ float g_wst[WTOT];
__device__ float g_bst[BTOT];

// ---------------- packed f32x2 helpers (sm_103a) ----------------
__device__ __forceinline__ ull fma2(ull a, ull b, ull c) {
    ull d; asm("fma.rn.f32x2 %0,%1,%2,%3;" : "=l"(d) : "l"(a), "l"(b), "l"(c)); return d;
}
__device__ __forceinline__ ull mul2(ull a, ull b) {
    ull d; asm("mul.rn.f32x2 %0,%1,%2;" : "=l"(d) : "l"(a), "l"(b)); return d;
}
__device__ __forceinline__ ull pack2(float lo, float hi) {
    ull d; asm("mov.b64 %0,{%1,%2};" : "=l"(d) : "f"(lo), "f"(hi)); return d;
}
__device__ __forceinline__ void unpack2(ull v, float& lo, float& hi) {
    asm("mov.b64 {%0,%1},%2;" : "=f"(lo), "=f"(hi) : "l"(v));
}

#define ONE2     0x3F8000003F800000ull
#define NEGONE2  0xBF800000BF800000ull
#define NEGTWO2  0xC0000000C0000000ull
#define SIX2     0x40C0000040C00000ull
#define NEGFOUR2 0xC0800000C0800000ull
#define NEGSIX2  0xC0C00000C0C00000ull

// ---------------- lb/ub reduction ----------------
__device__ unsigned g_pmin[GPART];
__device__ unsigned g_pmax[GPART];

__device__ __forceinline__ unsigned enc_f(float f) {
    unsigned u = __float_as_uint(f);
    return (u & 0x80000000u) ? ~u : (u | 0x80000000u);
}
__device__ __forceinline__ float dec_f(unsigned e) {
    unsigned u = (e & 0x80000000u) ? (e ^ 0x80000000u) : ~e;
    return __uint_as_float(u);
}

__global__ void k_partial_minmax(const float* __restrict__ X, int n) {
    __shared__ unsigned smn[8], smx[8];
    unsigned mn = 0xFFFFFFFFu, mx = 0u;
    for (int i = blockIdx.x * blockDim.x + threadIdx.x; i < n;
         i += gridDim.x * blockDim.x) {
        unsigned e = enc_f(X[3 * i]);
        mn = min(mn, e); mx = max(mx, e);
    }
    #pragma unroll
    for (int o = 16; o; o >>= 1) {
        mn = min(mn, __shfl_xor_sync(0xffffffffu, mn, o));
        mx = max(mx, __shfl_xor_sync(0xffffffffu, mx, o));
    }
    int w = threadIdx.x >> 5;
    if ((threadIdx.x & 31) == 0) { smn[w] = mn; smx[w] = mx; }
    __syncthreads();
    if (threadIdx.x == 0) {
        #pragma unroll
        for (int i = 1; i < 8; i++) { mn = min(mn, smn[i]); mx = max(mx, smx[i]); }
        g_pmin[blockIdx.x] = mn;
        g_pmax[blockIdx.x] = mx;
    }
}

// repack weights into padded layout in __device__ staging
__global__ void k_repack(const float* __restrict__ W1, const float* __restrict__ b1,
                         const float* __restrict__ W2, const float* __restrict__ b2,
                         const float* __restrict__ W3, const float* __restrict__ b3,
                         const float* __restrict__ W4, const float* __restrict__ b4,
                         const float* __restrict__ W5, const float* __restrict__ b5,
                         const float* __restrict__ W6, const float* __restrict__ b6,
                         const float* __restrict__ W7, const float* __restrict__ b7,
                         const float* __restrict__ W8, const float* __restrict__ b8) {
    const int WOFF[8] = {0, 12, 72, 472, 872, 1272, 1672, 2072};
    const int LDIN[8] = {3, 3, 20, 20, 20, 20, 20, 20};
    const int DSRC[8] = {3, 20, 20, 20, 20, 20, 20, 2};
    const int DPAD[8] = {4, 20, 20, 20, 20, 20, 20, 4};
    const int BOFF[8] = {0, 4, 24, 44, 64, 84, 104, 124};
    const float* Wg[8] = {W1, W2, W3, W4, W5, W6, W7, W8};
    const float* Bg[8] = {b1, b2, b3, b4, b5, b6, b7, b8};
    int tid = threadIdx.x;
    #pragma unroll
    for (int l = 0; l < 8; l++) {
        int tot = LDIN[l] * DPAD[l];
        for (int i = tid; i < tot; i += NTHREADS) {
            int r = i / DPAD[l], c = i % DPAD[l];
            g_wst[WOFF[l] + i] = (c < DSRC[l]) ? Wg[l][r * DSRC[l] + c] : 0.0f;
        }
        for (int i = tid; i < DPAD[l]; i += NTHREADS)
            g_bst[BOFF[l] + i] = (i < DSRC[l]) ? Bg[l][i] : 0.0f;
    }
}

// Jet order: 0:val 1:x 2:y 3:t 4:xx 5:xy 6:yy 7:xt 8:yt 9:xxx 10:xxy 11:xyy 12:yyy
// S layout per warp (ull units): [(g*2+s)*130 + jet*10 + q], q = unit-pair index.

template <int DIN, int DOUTP, int NQ, bool LAST>
__device__ __forceinline__ void layer(
    float (&ha)[20], float (&hb)[20],
    int woff, int boff,
    ull* __restrict__ Sw, int g, int l16, bool isj0, bool jvalid,
    float* __restrict__ out, int n, int wbase, float l1, float l2)
{
    constexpr int NCU = DOUTP / 2;
    constexpr int NC2 = DOUTP / 4;
    static_assert(DOUTP % 4 == 0, "pad DOUT");

    ull za[NCU], zb[NCU];
    #pragma unroll
    for (int c = 0; c < NC2; c++) {
        const float4 b = *reinterpret_cast<const float4*>(&c_b[boff + 4 * c]);
        za[2 * c]     = isj0 ? pack2(b.x, b.y) : 0ull;
        za[2 * c + 1] = isj0 ? pack2(b.z, b.w) : 0ull;
        zb[2 * c]     = za[2 * c];
        zb[2 * c + 1] = za[2 * c + 1];
    }
    #pragma unroll
    for (int i = 0; i < DIN; i++) {
        ull sa = pack2(ha[i], ha[i]);
        ull sb = pack2(hb[i], hb[i]);
        #pragma unroll
        for (int c = 0; c < NC2; c++) {
            const float4 w = *reinterpret_cast<const float4*>(&c_W[woff + i * DOUTP + 4 * c]);
            ull w01 = pack2(w.x, w.y);
            ull w23 = pack2(w.z, w.w);
            za[2 * c]     = fma2(sa, w01, za[2 * c]);
            za[2 * c + 1] = fma2(sa, w23, za[2 * c + 1]);
            zb[2 * c]     = fma2(sb, w01, zb[2 * c]);
            zb[2 * c + 1] = fma2(sb, w23, zb[2 * c + 1]);
        }
    }

    __syncwarp();
    if (jvalid) {
        ulonglong2* r0 = reinterpret_cast<ulonglong2*>(Sw + ((g * 2 + 0) * 13 + l16) * 10);
        ulonglong2* r1 = reinterpret_cast<ulonglong2*>(Sw + ((g * 2 + 1) * 13 + l16) * 10);
        #pragma unroll
        for (int c = 0; c < NC2; c++) {
            r0[c] = make_ulonglong2(za[2 * c], za[2 * c + 1]);
            r1[c] = make_ulonglong2(zb[2 * c], zb[2 * c + 1]);
        }
    }
    __syncwarp();

    #pragma unroll
    for (int s = 0; s < 2; s++) {
        if (l16 < NQ) {
            const int base = (g * 2 + s) * 130 + l16;
            ull zj[13];
            #pragma unroll
            for (int jj = 0; jj < 13; jj++) zj[jj] = Sw[base + jj * 10];

            float t0, t1; unpack2(zj[0], t0, t1);
            ull t   = pack2(tanhf(t0), tanhf(t1));
            ull hq  = mul2(t, t);
            ull sv  = fma2(hq, NEGONE2, ONE2);     // s = 1 - t^2
            ull C   = fma2(hq, SIX2, NEGTWO2);     // 6t^2 - 2
            ull n2h = mul2(t, NEGTWO2);
            ull n4h = mul2(t, NEGFOUR2);
            ull n6h = mul2(t, NEGSIX2);
            ull p11 = mul2(zj[1], zj[1]);
            ull p12 = mul2(zj[1], zj[2]);
            ull p22 = mul2(zj[2], zj[2]);
            ull p13 = mul2(zj[1], zj[3]);
            ull p23 = mul2(zj[2], zj[3]);

            ull hj[13];
            hj[0] = t;
            hj[1] = mul2(sv, zj[1]);
            hj[2] = mul2(sv, zj[2]);
            hj[3] = mul2(sv, zj[3]);
            hj[4] = mul2(sv, fma2(n2h, p11, zj[4]));
            hj[5] = mul2(sv, fma2(n2h, p12, zj[5]));
            hj[6] = mul2(sv, fma2(n2h, p22, zj[6]));
            hj[7] = mul2(sv, fma2(n2h, p13, zj[7]));
            hj[8] = mul2(sv, fma2(n2h, p23, zj[8]));
            {   // xxx
                ull r = fma2(n6h, mul2(zj[1], zj[4]), zj[9]);
                r = fma2(C, mul2(zj[1], p11), r);
                hj[9] = mul2(sv, r);
            }
            {   // xxy
                ull r = fma2(n2h, mul2(zj[2], zj[4]), zj[10]);
                r = fma2(n4h, mul2(zj[1], zj[5]), r);
                r = fma2(C, mul2(p11, zj[2]), r);
                hj[10] = mul2(sv, r);
            }
            {   // xyy
                ull r = fma2(n4h, mul2(zj[2], zj[5]), zj[11]);
                r = fma2(n2h, mul2(zj[1], zj[6]), r);
                r = fma2(C, mul2(zj[1], p22), r);
                hj[11] = mul2(sv, r);
            }
            {   // yyy
                ull r = fma2(n6h, mul2(zj[2], zj[6]), zj[12]);
                r = fma2(C, mul2(zj[2], p22), r);
                hj[12] = mul2(sv, r);
            }

            if (!LAST) {
                #pragma unroll
                for (int jj = 0; jj < 13; jj++) Sw[base + jj * 10] = hj[jj];
            } else {
                const int pt = wbase + g * 2 + s;
                if (pt < n) {
                    float ps[13], pr0 = 0.f, pr1 = 0.f, pr2 = 0.f;
                    #pragma unroll
                    for (int jj = 0; jj < 13; jj++) {
                        float a, b; unpack2(hj[jj], a, b);
                        ps[jj] = a;
                        if (jj == 0) pr0 = b;
                        else if (jj == 1) pr1 = b;
                        else if (jj == 2) pr2 = b;
                    }
                    float u    =  ps[2];
                    float v    = -ps[1];
                    float p_x  =  pr1;
                    float p_y  =  pr2;
                    float u_t  =  ps[8];
                    float u_x  =  ps[5];
                    float u_y  =  ps[6];
                    float v_t  = -ps[7];
                    float v_x  = -ps[4];
                    float v_y  = -ps[5];
                    float u_xx =  ps[10];
                    float u_yy =  ps[12];
                    float v_xx = -ps[9];
                    float v_yy = -ps[11];
                    float f_u = u_t + l1 * (u * u_x + v * u_y) + p_x - l2 * (u_xx + u_yy);
                    float f_v = v_t + l1 * (u * v_x + v * v_y) + p_y - l2 * (v_xx + v_yy);
                    out[0 * n + pt] = u;
                    out[1 * n + pt] = v;
                    out[2 * n + pt] = pr0;
                    out[3 * n + pt] = f_u;
                    out[4 * n + pt] = f_v;
                }
            }
        }
    }
    __syncwarp();

    if (!LAST && jvalid) {
        const ulonglong2* r0 = reinterpret_cast<const ulonglong2*>(Sw + ((g * 2 + 0) * 13 + l16) * 10);
        const ulonglong2* r1 = reinterpret_cast<const ulonglong2*>(Sw + ((g * 2 + 1) * 13 + l16) * 10);
        #pragma unroll
        for (int c = 0; c < NC2; c++) {
            ulonglong2 v0 = r0[c];
            unpack2(v0.x, ha[4 * c],     ha[4 * c + 1]);
            unpack2(v0.y, ha[4 * c + 2], ha[4 * c + 3]);
            ulonglong2 v1 = r1[c];
            unpack2(v1.x, hb[4 * c],     hb[4 * c + 1]);
            unpack2(v1.y, hb[4 * c + 2], hb[4 * c + 3]);
        }
    }
}

__global__ void __launch_bounds__(NTHREADS, 2)
pinn_kernel(const float* __restrict__ X,
            const float* __restrict__ lam1p, const float* __restrict__ lam2p,
            float* __restrict__ out, int n)
{
    __shared__ __align__(16) ull Ssh[8 * 528];

    const int tid = threadIdx.x;

    // fold lb/ub partials (uniform, broadcast)
    unsigned mn = 0xFFFFFFFFu, mx = 0u;
    #pragma unroll
    for (int i = 0; i < GPART; i++) {
        mn = min(mn, g_pmin[i]);
        mx = max(mx, g_pmax[i]);
    }
    const float lb = dec_f(mn);
    const float ub = dec_f(mx);
    const float sc = 2.0f / (ub - lb);
    const float l1 = lam1p[0];
    const float l2 = lam2p[0];

    const int warp = tid >> 5;
    const int lane = tid & 31;
    const int g    = lane >> 4;
    const int l16  = lane & 15;
    const bool jvalid = (l16 < 13);
    const bool isj0   = (l16 == 0);
    ull* Sw = Ssh + warp * 528;

    const int wbase = (blockIdx.x * 8 + warp) * 4;   // 4 points per warp
    const int ptA = min(wbase + g * 2,     n - 1);
    const int ptB = min(wbase + g * 2 + 1, n - 1);

    float ha[20], hb[20];
    #pragma unroll
    for (int k = 0; k < 20; k++) { ha[k] = 0.0f; hb[k] = 0.0f; }
    if (isj0) {
        ha[0] = sc * (X[3 * ptA + 0] - lb) - 1.0f;
        ha[1] = sc * (X[3 * ptA + 1] - lb) - 1.0f;
        ha[2] = sc * (X[3 * ptA + 2] - lb) - 1.0f;
        hb[0] = sc * (X[3 * ptB + 0] - lb) - 1.0f;
        hb[1] = sc * (X[3 * ptB + 1] - lb) - 1.0f;
        hb[2] = sc * (X[3 * ptB + 2] - lb) - 1.0f;
    } else if (l16 == 1) { ha[0] = sc; hb[0] = sc; }
    else if (l16 == 2)   { ha[1] = sc; hb[1] = sc; }
    else if (l16 == 3)   { ha[2] = sc; hb[2] = sc; }

    layer<3, 4, 2, false>(ha, hb, 0, 0,  Sw, g, l16, isj0, jvalid, out, n, wbase, l1, l2);
    layer<3, 20, 10, false>(ha, hb, 12, 4, Sw, g, l16, isj0, jvalid, out, n, wbase, l1, l2);
    #pragma unroll 1
    for (int l = 0; l < 5; l++) {
        layer<20, 20, 10, false>(ha, hb, 72 + 400 * l, 24 + 20 * l,
                                 Sw, g, l16, isj0, jvalid, out, n, wbase, l1, l2);
    }
    layer<20, 4, 1, true>(ha, hb, 2072, 124, Sw, g, l16, isj0, jvalid, out, n, wbase, l1, l2);
}

extern "C" void kernel_launch(void* const* d_in, const int* in_sizes, int n_in,
                              void* d_out, int out_size) {
    const float* X    = (const float*)d_in[0];
    const float* W1   = (const float*)d_in[1];
    const float* b1   = (const float*)d_in[2];
    const float* W2   = (const float*)d_in[3];
    const float* b2   = (const float*)d_in[4];
    const float* W3   = (const float*)d_in[5];
    const float* b3   = (const float*)d_in[6];
    const float* W4   = (const float*)d_in[7];
    const float* b4   = (const float*)d_in[8];
    const float* W5   = (const float*)d_in[9];
    const float* b5   = (const float*)d_in[10];
    const float* W6   = (const float*)d_in[11];
    const float* b6   = (const float*)d_in[12];
    const float* W7   = (const float*)d_in[13];
    const float* b7   = (const float*)d_in[14];
    const float* W8   = (const float*)d_in[15];
    const float* b8   = (const float*)d_in[16];
    const float* lam1 = (const float*)d_in[17];
    const float* lam2 = (const float*)d_in[18];
    float* out = (float*)d_out;

    int n = in_sizes[0] / 3;

    k_repack<<<1, NTHREADS>>>(W1, b1, W2, b2, W3, b3, W4, b4,
                              W5, b5, W6, b6, W7, b7, W8, b8);
    void* wsrc = nullptr; void* bsrc = nullptr;
    cudaGetSymbolAddress(&wsrc, g_wst);
    cudaGetSymbolAddress(&bsrc, g_bst);
    cudaMemcpyToSymbolAsync(c_W, wsrc, WTOT * sizeof(float), 0, cudaMemcpyDeviceToDevice);
    cudaMemcpyToSymbolAsync(c_b, bsrc, BTOT * sizeof(float), 0, cudaMemcpyDeviceToDevice);

    k_partial_minmax<<<GPART, 256>>>(X, n);

    int blocks = (n + 31) / 32;   // 32 points per block
    pinn_kernel<<<blocks, NTHREADS>>>(X, lam1, lam2, out, n);
}